// round 7
// baseline (speedup 1.0000x reference)
#include <cuda_runtime.h>
#include <cstdint>

// Problem constants
#define NB     4
#define LSEQ   4096
#define ROWS   16384
#define DIMV   512
#define HID2   2048
#define HIDV   1024
#define QKD    128
#define OUTD   8

// ------------------------- scratch (static device globals) -------------------
__device__ float g_normed[(size_t)ROWS * DIMV];      //  32 MB (tf32-rounded)
__device__ float g_WhR   [(size_t)DIMV * HID2];      //   4 MB (tf32-rounded)
__device__ float g_WqkR  [(size_t)DIMV * QKD];       // 256 KB (tf32-rounded)
__device__ float g_hidden[(size_t)ROWS * HID2];      // 128 MB (v tf32 | gate fp32)
__device__ float g_Z     [(size_t)ROWS * QKD];       //   8 MB
__device__ float g_q     [(size_t)ROWS * QKD];       //   8 MB (tf32)
__device__ float g_k     [(size_t)ROWS * QKD];       //   8 MB (tf32)
__device__ float g_A     [(size_t)NB * LSEQ * LSEQ]; // 268 MB (tf32)
__device__ float g_V     [(size_t)ROWS * HIDV];      //  64 MB

// ------------------------------ helpers --------------------------------------
__device__ __forceinline__ uint32_t f2tf32(float f) {
    uint32_t r;
    asm("cvt.rna.tf32.f32 %0, %1;" : "=r"(r) : "f"(f));
    return r;
}
__device__ __forceinline__ float tf32r(float f) { return __uint_as_float(f2tf32(f)); }

__device__ __forceinline__ uint32_t smem_u32(const void* p) {
    uint32_t a;
    asm("{ .reg .u64 t; cvta.to.shared.u64 t, %1; cvt.u32.u64 %0, t; }" : "=r"(a) : "l"(p));
    return a;
}
__device__ __forceinline__ void cp16(uint32_t s, const float* g) {
    asm volatile("cp.async.cg.shared.global [%0], [%1], 16;" :: "r"(s), "l"(g));
}
#define CP_COMMIT() asm volatile("cp.async.commit_group;" ::: "memory")
#define CP_WAIT0()  asm volatile("cp.async.wait_group 0;" ::: "memory")
#define CP_WAIT1()  asm volatile("cp.async.wait_group 1;" ::: "memory")

__device__ __forceinline__ void mma_tf32(float* c, const uint32_t* a, const uint32_t* b) {
    asm volatile(
        "mma.sync.aligned.m16n8k8.row.col.f32.tf32.tf32.f32 "
        "{%0,%1,%2,%3},{%4,%5,%6,%7},{%8,%9},{%0,%1,%2,%3};"
        : "+f"(c[0]), "+f"(c[1]), "+f"(c[2]), "+f"(c[3])
        : "r"(a[0]), "r"(a[1]), "r"(a[2]), "r"(a[3]), "r"(b[0]), "r"(b[1]));
}

// ------------------------------ LayerNorm (tf32 out) -------------------------
__global__ void ln_kernel(const float* __restrict__ x, const float* __restrict__ g,
                          const float* __restrict__ b, float* __restrict__ o) {
    int row = blockIdx.x;
    int t = threadIdx.x;
    const float4* xr = (const float4*)(x + (size_t)row * DIMV);
    float4 xv = xr[t];
    float s  = xv.x + xv.y + xv.z + xv.w;
    float ss = xv.x*xv.x + xv.y*xv.y + xv.z*xv.z + xv.w*xv.w;
    #pragma unroll
    for (int off = 16; off; off >>= 1) {
        s  += __shfl_xor_sync(0xffffffffu, s,  off);
        ss += __shfl_xor_sync(0xffffffffu, ss, off);
    }
    __shared__ float sh_s[4], sh_ss[4];
    if ((t & 31) == 0) { sh_s[t >> 5] = s; sh_ss[t >> 5] = ss; }
    __syncthreads();
    s  = sh_s[0] + sh_s[1] + sh_s[2] + sh_s[3];
    ss = sh_ss[0] + sh_ss[1] + sh_ss[2] + sh_ss[3];
    float mu  = s * (1.0f / DIMV);
    float var = ss * (1.0f / DIMV) - mu * mu;
    float inv = rsqrtf(var + 1e-5f);
    float4 gv = ((const float4*)g)[t];
    float4 bv = ((const float4*)b)[t];
    float4 ov;
    ov.x = tf32r((xv.x - mu) * inv * gv.x + bv.x);
    ov.y = tf32r((xv.y - mu) * inv * gv.y + bv.y);
    ov.z = tf32r((xv.z - mu) * inv * gv.z + bv.z);
    ov.w = tf32r((xv.w - mu) * inv * gv.w + bv.w);
    ((float4*)(o + (size_t)row * DIMV))[t] = ov;
}

// --------------------------- tf32 rounding copy ------------------------------
__global__ void round_tf32(const float* __restrict__ s, float* __restrict__ d, int n) {
    int i = blockIdx.x * blockDim.x + threadIdx.x;
    if (i < n) d[i] = tf32r(s[i]);
}

// --------------------------- tf32 tensor-core GEMM ---------------------------
// C[M,N] = A[M,K] @ B   (BT=false: B is [K,N] row-major; BT=true: B is [N,K])
// All MMA operands pre-rounded to tf32 by producers -> HW truncation is exact.
// CTA tile 128x128, BK=32, 2-stage cp.async pipeline.
// 4 warps in 2x2 grid, warp tile 64x64 (4x8 m16n8k8 frags) -> LDS/MMA ratio 1.0.
// EPI 0: v = silu(acc + aux[n]);  tf32-round when n < HIDV (v half / Z), raw otherwise (gate)
// EPI 1: tf32(relu(acc*scale)^2)
// EPI 2: acc * aux[m*ldaux + n]
template<int EPI, bool BT>
__global__ void __launch_bounds__(128, 2)
tmma_gemm(const float* __restrict__ Ag, const float* __restrict__ Bg,
          float* __restrict__ Cg, int K, int lda, int ldb, int ldc,
          size_t sA, size_t sB, size_t sC,
          const float* __restrict__ aux, int ldaux, size_t sAux, float scale)
{
    constexpr int ASTG = 128 * 36;                 // floats per A stage (pitch 36)
    constexpr int BPITCH = BT ? 36 : 136;
    constexpr int BSTG = BT ? (128 * 36) : (32 * 136);

    extern __shared__ float sm[];
    float* AsBase = sm;                  // 2 stages
    float* BsBase = sm + 2 * ASTG;       // 2 stages
    const uint32_t sbA = smem_u32(AsBase);
    const uint32_t sbB = smem_u32(BsBase);

    const float* A = Ag + blockIdx.z * sA;
    const float* B = Bg + blockIdx.z * sB;
    float*       C = Cg + blockIdx.z * sC;
    const float* ax = aux + blockIdx.z * sAux;

    const int tid  = threadIdx.x;
    const int warp = tid >> 5;
    const int lane = tid & 31;
    const int grp  = lane >> 2;
    const int tig  = lane & 3;
    const int mw   = (warp >> 1) * 64;   // 0, 64
    const int nw   = (warp & 1) * 64;    // 0, 64
    const int m0 = blockIdx.y * 128, n0 = blockIdx.x * 128;

    float acc[4][8][4];
    #pragma unroll
    for (int mi = 0; mi < 4; mi++)
        #pragma unroll
        for (int ni = 0; ni < 8; ni++)
            #pragma unroll
            for (int r = 0; r < 4; r++) acc[mi][ni][r] = 0.0f;

    auto load_stage = [&](int st, int k0) {
        // A tile: 128 x 32 floats = 1024 16B chunks, 8/thread
        #pragma unroll
        for (int l = 0; l < 8; l++) {
            int fid = tid + l * 128;
            int r = fid >> 3, ch = fid & 7;
            cp16(sbA + (uint32_t)(st * ASTG + r * 36 + ch * 4) * 4,
                 A + (size_t)(m0 + r) * lda + k0 + ch * 4);
        }
        #pragma unroll
        for (int l = 0; l < 8; l++) {
            int fid = tid + l * 128;
            if (!BT) {   // 32 x 128 floats
                int r = fid >> 5, ch = fid & 31;
                cp16(sbB + (uint32_t)(st * BSTG + r * BPITCH + ch * 4) * 4,
                     B + (size_t)(k0 + r) * ldb + n0 + ch * 4);
            } else {     // 128 x 32 floats
                int n = fid >> 3, ch = fid & 7;
                cp16(sbB + (uint32_t)(st * BSTG + n * BPITCH + ch * 4) * 4,
                     B + (size_t)(n0 + n) * ldb + k0 + ch * 4);
            }
        }
        CP_COMMIT();
    };

    const int niter = K / 32;
    load_stage(0, 0);

    for (int it = 0; it < niter; it++) {
        if (it + 1 < niter) { load_stage((it + 1) & 1, (it + 1) * 32); CP_WAIT1(); }
        else                { CP_WAIT0(); }
        __syncthreads();

        const float* As = AsBase + (it & 1) * ASTG;
        const float* Bs = BsBase + (it & 1) * BSTG;

        #pragma unroll
        for (int ks = 0; ks < 32; ks += 8) {
            uint32_t afr[4][4], bfr[8][2];
            #pragma unroll
            for (int mi = 0; mi < 4; mi++) {
                int r = mw + mi * 16 + grp;
                afr[mi][0] = __float_as_uint(As[r * 36 + ks + tig]);
                afr[mi][1] = __float_as_uint(As[(r + 8) * 36 + ks + tig]);
                afr[mi][2] = __float_as_uint(As[r * 36 + ks + tig + 4]);
                afr[mi][3] = __float_as_uint(As[(r + 8) * 36 + ks + tig + 4]);
            }
            #pragma unroll
            for (int ni = 0; ni < 8; ni++) {
                int c = nw + ni * 8 + grp;
                if (!BT) {
                    bfr[ni][0] = __float_as_uint(Bs[(ks + tig) * BPITCH + c]);
                    bfr[ni][1] = __float_as_uint(Bs[(ks + tig + 4) * BPITCH + c]);
                } else {
                    bfr[ni][0] = __float_as_uint(Bs[c * BPITCH + ks + tig]);
                    bfr[ni][1] = __float_as_uint(Bs[c * BPITCH + ks + tig + 4]);
                }
            }
            #pragma unroll
            for (int mi = 0; mi < 4; mi++)
                #pragma unroll
                for (int ni = 0; ni < 8; ni++)
                    mma_tf32(acc[mi][ni], afr[mi], bfr[ni]);
        }
        __syncthreads();
    }

    // ------------------------------ epilogue ---------------------------------
    #pragma unroll
    for (int mi = 0; mi < 4; mi++) {
        #pragma unroll
        for (int half = 0; half < 2; half++) {
            int m = m0 + mw + mi * 16 + grp + half * 8;
            #pragma unroll
            for (int ni = 0; ni < 8; ni++) {
                int n = n0 + nw + ni * 8 + tig * 2;
                float v0 = acc[mi][ni][half * 2 + 0];
                float v1 = acc[mi][ni][half * 2 + 1];
                if (EPI == 0) {
                    v0 += ax[n];     v1 += ax[n + 1];
                    v0 = v0 / (1.0f + __expf(-v0));
                    v1 = v1 / (1.0f + __expf(-v1));
                    if (n < HIDV)     v0 = tf32r(v0);   // v half / Z: feeds next MMA
                    if (n + 1 < HIDV) v1 = tf32r(v1);
                } else if (EPI == 1) {
                    float t0 = fmaxf(v0 * scale, 0.0f);
                    float t1 = fmaxf(v1 * scale, 0.0f);
                    v0 = tf32r(t0 * t0); v1 = tf32r(t1 * t1);
                } else {
                    v0 *= ax[(size_t)m * ldaux + n];
                    v1 *= ax[(size_t)m * ldaux + n + 1];
                }
                *(float2*)(C + (size_t)m * ldc + n) = make_float2(v0, v1);
            }
        }
    }
}

// ---------------------------- q/k affine from Z (tf32 out) -------------------
__global__ void qk_kernel(const float* __restrict__ Z,
                          const float* __restrict__ gamma, const float* __restrict__ beta,
                          float* __restrict__ q, float* __restrict__ k) {
    size_t idx = (size_t)blockIdx.x * blockDim.x + threadIdx.x;
    if (idx >= (size_t)ROWS * QKD) return;
    int d = (int)(idx & (QKD - 1));
    float z = Z[idx];
    q[idx] = tf32r(z * gamma[d]       + beta[d]);
    k[idx] = tf32r(z * gamma[QKD + d] + beta[QKD + d]);
}

// ------------------------- output projection (1024 -> 8) ---------------------
__global__ void out_kernel(const float* __restrict__ Vg, const float* __restrict__ Wo,
                           const float* __restrict__ bo, float* __restrict__ out) {
    int row  = blockIdx.x * (blockDim.x >> 5) + (threadIdx.x >> 5);
    int lane = threadIdx.x & 31;
    const float* vr = Vg + (size_t)row * HIDV;
    float acc[OUTD];
    #pragma unroll
    for (int o = 0; o < OUTD; o++) acc[o] = 0.0f;
    for (int kk = lane; kk < HIDV; kk += 32) {
        float v = vr[kk];
        const float* w = Wo + (size_t)kk * OUTD;
        #pragma unroll
        for (int o = 0; o < OUTD; o++) acc[o] += v * w[o];
    }
    #pragma unroll
    for (int o = 0; o < OUTD; o++) {
        #pragma unroll
        for (int off = 16; off; off >>= 1)
            acc[o] += __shfl_xor_sync(0xffffffffu, acc[o], off);
    }
    if (lane < OUTD) out[(size_t)row * OUTD + lane] = acc[lane] + bo[lane];
}

// --------------------------------- launch ------------------------------------
extern "C" void kernel_launch(void* const* d_in, const int* in_sizes, int n_in,
                              void* d_out, int out_size) {
    const float* x     = (const float*)d_in[0];
    const float* ln_g  = (const float*)d_in[1];
    const float* ln_b  = (const float*)d_in[2];
    const float* Wh    = (const float*)d_in[3];
    const float* bh    = (const float*)d_in[4];
    const float* Wqk   = (const float*)d_in[5];
    const float* bqk   = (const float*)d_in[6];
    const float* gamma = (const float*)d_in[7];
    const float* beta  = (const float*)d_in[8];
    const float* Wo    = (const float*)d_in[9];
    const float* bo    = (const float*)d_in[10];
    float* out = (float*)d_out;

    float *normed, *WhR, *WqkR, *hidden, *Z, *q, *k, *A, *V;
    cudaGetSymbolAddress((void**)&normed, g_normed);
    cudaGetSymbolAddress((void**)&WhR,    g_WhR);
    cudaGetSymbolAddress((void**)&WqkR,   g_WqkR);
    cudaGetSymbolAddress((void**)&hidden, g_hidden);
    cudaGetSymbolAddress((void**)&Z,      g_Z);
    cudaGetSymbolAddress((void**)&q,      g_q);
    cudaGetSymbolAddress((void**)&k,      g_k);
    cudaGetSymbolAddress((void**)&A,      g_A);
    cudaGetSymbolAddress((void**)&V,      g_V);

    // dynamic smem: A 2*128*36*4 = 36864 B; B nonBT 2*32*136*4 = 34816 B; BT 36864 B
    const int SM_NBT = 36864 + 34816;   // 71680
    const int SM_BT  = 36864 + 36864;   // 73728
    static bool attr_done = false;
    if (!attr_done) {
        cudaFuncSetAttribute(tmma_gemm<0,false>, cudaFuncAttributeMaxDynamicSharedMemorySize, SM_NBT);
        cudaFuncSetAttribute(tmma_gemm<1,true >, cudaFuncAttributeMaxDynamicSharedMemorySize, SM_BT);
        cudaFuncSetAttribute(tmma_gemm<2,false>, cudaFuncAttributeMaxDynamicSharedMemorySize, SM_NBT);
        attr_done = true;
    }

    // 0. tf32-round the weights
    round_tf32<<<(DIMV * HID2 + 255) / 256, 256>>>(Wh,  WhR,  DIMV * HID2);
    round_tf32<<<(DIMV * QKD  + 255) / 256, 256>>>(Wqk, WqkR, DIMV * QKD);

    // 1. LayerNorm (tf32-rounded output)
    ln_kernel<<<ROWS, 128>>>(x, ln_g, ln_b, normed);

    // 2. hidden = silu(normed @ Wh + bh)   [16384, 2048]  (v half tf32, gate fp32)
    tmma_gemm<0, false><<<dim3(HID2 / 128, ROWS / 128, 1), 128, SM_NBT>>>(
        normed, WhR, hidden, DIMV, DIMV, HID2, HID2,
        0, 0, 0, bh, 0, 0, 0.0f);

    // 3. Z = silu(normed @ Wqk + bqk)      [16384, 128]
    tmma_gemm<0, false><<<dim3(1, ROWS / 128, 1), 128, SM_NBT>>>(
        normed, WqkR, Z, DIMV, DIMV, QKD, QKD,
        0, 0, 0, bqk, 0, 0, 0.0f);

    // 4. q, k (tf32-rounded)
    {
        size_t nel = (size_t)ROWS * QKD;
        qk_kernel<<<(unsigned)((nel + 255) / 256), 256>>>(Z, gamma, beta, q, k);
    }

    // 5. A = tf32(relu(q @ k^T / L)^2)   per batch  [4096, 4096]
    tmma_gemm<1, true><<<dim3(LSEQ / 128, LSEQ / 128, NB), 128, SM_BT>>>(
        q, k, A, QKD, QKD, QKD, LSEQ,
        (size_t)LSEQ * QKD, (size_t)LSEQ * QKD, (size_t)LSEQ * LSEQ,
        bo /*unused*/, 0, 0, 1.0f / LSEQ);

    // 6. V = (A @ v) * gate   per batch  [4096, 1024]
    tmma_gemm<2, false><<<dim3(HIDV / 128, LSEQ / 128, NB), 128, SM_NBT>>>(
        A, hidden, V, LSEQ, LSEQ, HID2, HIDV,
        (size_t)LSEQ * LSEQ, (size_t)LSEQ * HID2, (size_t)LSEQ * HIDV,
        hidden + HIDV, HID2, (size_t)LSEQ * HID2, 0.0f);

    // 7. out = V @ Wo + bo
    out_kernel<<<ROWS / 8, 256>>>(V, Wo, bo, out);
}

// round 8
// speedup vs baseline: 1.0718x; 1.0718x over previous
#include <cuda_runtime.h>
#include <cstdint>

// Problem constants
#define NB     4
#define LSEQ   4096
#define ROWS   16384
#define DIMV   512
#define HID2   2048
#define HIDV   1024
#define QKD    128
#define OUTD   8

// ------------------------- scratch (static device globals) -------------------
__device__ float g_normed[(size_t)ROWS * DIMV];      // quad layout, tf32
__device__ float g_WhR   [(size_t)DIMV * HID2];      // row-major [k][n], tf32
__device__ float g_WqkR  [(size_t)DIMV * QKD];       // row-major [k][n], tf32
__device__ float g_hidden[(size_t)ROWS * HID2];      // [m][2048]: v tf32 | gate fp32
__device__ float g_q     [(size_t)ROWS * QKD];       // quad layout, tf32
__device__ float g_k     [(size_t)ROWS * QKD];       // row-major, k-pair-permuted, tf32
__device__ float g_A     [(size_t)NB * LSEQ * LSEQ]; // quad layout per batch, tf32
__device__ float g_V     [(size_t)ROWS * HIDV];      // [m][1024]

// ------------------------------ helpers --------------------------------------
__device__ __forceinline__ uint32_t f2tf32(float f) {
    uint32_t r;
    asm("cvt.rna.tf32.f32 %0, %1;" : "=r"(r) : "f"(f));
    return r;
}
__device__ __forceinline__ float tf32r(float f) { return __uint_as_float(f2tf32(f)); }

__device__ __forceinline__ uint32_t smem_u32(const void* p) {
    uint32_t a;
    asm("{ .reg .u64 t; cvta.to.shared.u64 t, %1; cvt.u32.u64 %0, t; }" : "=r"(a) : "l"(p));
    return a;
}
__device__ __forceinline__ void cp16(uint32_t s, const float* g) {
    asm volatile("cp.async.cg.shared.global [%0], [%1], 16;" :: "r"(s), "l"(g));
}
#define CP_COMMIT() asm volatile("cp.async.commit_group;" ::: "memory")
#define CP_WAIT0()  asm volatile("cp.async.wait_group 0;" ::: "memory")
#define CP_WAIT1()  asm volatile("cp.async.wait_group 1;" ::: "memory")

__device__ __forceinline__ void mma_tf32(float* c, const uint32_t* a, const uint32_t* b) {
    asm volatile(
        "mma.sync.aligned.m16n8k8.row.col.f32.tf32.tf32.f32 "
        "{%0,%1,%2,%3},{%4,%5,%6,%7},{%8,%9},{%0,%1,%2,%3};"
        : "+f"(c[0]), "+f"(c[1]), "+f"(c[2]), "+f"(c[3])
        : "r"(a[0]), "r"(a[1]), "r"(a[2]), "r"(a[3]), "r"(b[0]), "r"(b[1]));
}

// Quad layout: X[M][K] -> blocks of 16 rows x 8 cols (128 floats); within a
// block, element (m,k) at ((m&7)*4 + (k&3))*4 + ((k>>2)&1)*2 + ((m>>3)&1).
// A thread's m16n8k8 A-fragment is one contiguous 16B quad.
__device__ __forceinline__ size_t quad_off(int m, int k, int K8) {
    return ((size_t)(m >> 4) * K8 + (k >> 3)) * 128
         + (size_t)(((m & 7) * 4 + (k & 3)) * 4 + ((k >> 2) & 1) * 2 + ((m >> 3) & 1));
}
// k-pair permutation within 8-groups: [0,4,1,5,2,6,3,7]
__device__ __forceinline__ int kperm(int k) {
    return (k & ~7) + (k & 3) * 2 + ((k >> 2) & 1);
}

// ------------------------------ LayerNorm (quad tf32 out) --------------------
__global__ void ln_kernel(const float* __restrict__ x, const float* __restrict__ g,
                          const float* __restrict__ b, float* __restrict__ o) {
    int row = blockIdx.x;
    int t = threadIdx.x;
    const float4* xr = (const float4*)(x + (size_t)row * DIMV);
    float4 xv = xr[t];
    float s  = xv.x + xv.y + xv.z + xv.w;
    float ss = xv.x*xv.x + xv.y*xv.y + xv.z*xv.z + xv.w*xv.w;
    #pragma unroll
    for (int off = 16; off; off >>= 1) {
        s  += __shfl_xor_sync(0xffffffffu, s,  off);
        ss += __shfl_xor_sync(0xffffffffu, ss, off);
    }
    __shared__ float sh_s[4], sh_ss[4];
    if ((t & 31) == 0) { sh_s[t >> 5] = s; sh_ss[t >> 5] = ss; }
    __syncthreads();
    s  = sh_s[0] + sh_s[1] + sh_s[2] + sh_s[3];
    ss = sh_ss[0] + sh_ss[1] + sh_ss[2] + sh_ss[3];
    float mu  = s * (1.0f / DIMV);
    float var = ss * (1.0f / DIMV) - mu * mu;
    float inv = rsqrtf(var + 1e-5f);
    float4 gv = ((const float4*)g)[t];
    float4 bv = ((const float4*)b)[t];
    float r0 = tf32r((xv.x - mu) * inv * gv.x + bv.x);
    float r1 = tf32r((xv.y - mu) * inv * gv.y + bv.y);
    float r2 = tf32r((xv.z - mu) * inv * gv.z + bv.z);
    float r3 = tf32r((xv.w - mu) * inv * gv.w + bv.w);
    int d0 = t * 4;
    o[quad_off(row, d0 + 0, DIMV / 8)] = r0;
    o[quad_off(row, d0 + 1, DIMV / 8)] = r1;
    o[quad_off(row, d0 + 2, DIMV / 8)] = r2;
    o[quad_off(row, d0 + 3, DIMV / 8)] = r3;
}

// --------------------------- tf32 rounding copy ------------------------------
__global__ void round_tf32(const float* __restrict__ s, float* __restrict__ d, int n) {
    int i = blockIdx.x * blockDim.x + threadIdx.x;
    if (i < n) d[i] = tf32r(s[i]);
}

// --------------------------- tf32 tensor-core GEMM ---------------------------
// D[m][n] = sum_k A[m][k]*B-op;  A in quad layout (LDS.128 frags).
// BL=0: B row-major [K][N] (pitch 136, 2x LDS.32 frags)
// BL=1: B row-major [N][K] k-pair-permuted (pitch 40, LDS.64 frags)
// CTA 128x128, BK=32, 2-stage cp.async, 8 warps, warp tile 64x32.
// EPI 0 (Wh):  v = silu(acc+a0[n]); tf32 when n<HIDV (v half); raw (gate) else
// EPI 1 (qkT): A-out quad = tf32(relu(acc*scale)^2)
// EPI 2 (AV):  V = acc * a0[m*ldaux+n]
// EPI 3 (Z):   s = silu(acc+a0[n]); q quad = tf32(s*a1[n]+a2[n]);
//              k perm = tf32(s*a1[128+n]+a2[128+n])
template<int EPI, int BL>
__global__ void __launch_bounds__(256, 2)
tgemm(const float* __restrict__ Ag, int K8, size_t sA,
      const float* __restrict__ Bg, int ldb, size_t sB,
      float* __restrict__ C0, float* __restrict__ C1,
      int K, int ldc, size_t sC,
      const float* __restrict__ a0, const float* __restrict__ a1,
      const float* __restrict__ a2, int ldaux, size_t sAux, float scale)
{
    constexpr int ASTG = 4096;                 // floats per A stage (32 blocks x 128)
    constexpr int BPITCH = BL ? 40 : 136;
    constexpr int BSTG = BL ? (128 * 40) : (32 * 136);

    extern __shared__ float sm[];
    float* AsBase = sm;
    float* BsBase = sm + 2 * ASTG;
    const uint32_t sbA = smem_u32(AsBase);
    const uint32_t sbB = smem_u32(BsBase);

    const float* A = Ag + blockIdx.z * sA;
    const float* B = Bg + blockIdx.z * sB;
    float*       C = C0 + blockIdx.z * sC;
    const float* ax = a0 + blockIdx.z * sAux;

    const int tid  = threadIdx.x;
    const int warp = tid >> 5;
    const int lane = tid & 31;
    const int grp  = lane >> 2;
    const int tig  = lane & 3;
    const int mw   = (warp >> 2) * 64;   // 0, 64
    const int nw   = (warp & 3) * 32;    // 0, 32, 64, 96
    const int m0 = blockIdx.y * 128, n0 = blockIdx.x * 128;
    const int mbb = (mw >> 4);           // 0 or 4: warp's base m-block

    float acc[4][4][4];
    #pragma unroll
    for (int mi = 0; mi < 4; mi++)
        #pragma unroll
        for (int ni = 0; ni < 4; ni++)
            #pragma unroll
            for (int r = 0; r < 4; r++) acc[mi][ni][r] = 0.0f;

    auto load_stage = [&](int st, int k0) {
        // A: 32 quad-blocks x 128 floats = 1024 chunks, 4/thread
        #pragma unroll
        for (int l = 0; l < 4; l++) {
            int qc = tid + l * 256;
            int blk = qc >> 5, c = qc & 31;
            int mbl = blk >> 2, kbl = blk & 3;
            size_t gblk = (size_t)(m0 / 16 + mbl) * K8 + (k0 / 8 + kbl);
            cp16(sbA + (uint32_t)(st * ASTG + blk * 128 + c * 4) * 4,
                 A + gblk * 128 + c * 4);
        }
        #pragma unroll
        for (int l = 0; l < 4; l++) {
            int fid = tid + l * 256;
            if (BL == 0) {   // 32 rows x 128 floats
                int r = fid >> 5, ch = fid & 31;
                cp16(sbB + (uint32_t)(st * BSTG + r * BPITCH + ch * 4) * 4,
                     B + (size_t)(k0 + r) * ldb + n0 + ch * 4);
            } else {         // 128 rows x 32 floats (perm within rows is opaque)
                int r = fid >> 3, ch = fid & 7;
                cp16(sbB + (uint32_t)(st * BSTG + r * BPITCH + ch * 4) * 4,
                     B + (size_t)(n0 + r) * ldb + k0 + ch * 4);
            }
        }
        CP_COMMIT();
    };

    const int niter = K / 32;
    load_stage(0, 0);

    for (int it = 0; it < niter; it++) {
        if (it + 1 < niter) { load_stage((it + 1) & 1, (it + 1) * 32); CP_WAIT1(); }
        else                { CP_WAIT0(); }
        __syncthreads();

        const float* As = AsBase + (it & 1) * ASTG;
        const float* Bs = BsBase + (it & 1) * BSTG;

        #pragma unroll
        for (int ks = 0; ks < 32; ks += 8) {
            uint32_t afr[4][4], bfr[4][2];
            #pragma unroll
            for (int mi = 0; mi < 4; mi++) {
                float4 av = *(const float4*)(As + ((mbb + mi) * 4 + (ks >> 3)) * 128
                                                + (grp * 4 + tig) * 4);
                afr[mi][0] = __float_as_uint(av.x);
                afr[mi][1] = __float_as_uint(av.y);
                afr[mi][2] = __float_as_uint(av.z);
                afr[mi][3] = __float_as_uint(av.w);
            }
            #pragma unroll
            for (int ni = 0; ni < 4; ni++) {
                int c = nw + ni * 8 + grp;
                if (BL == 0) {
                    bfr[ni][0] = __float_as_uint(Bs[(ks + tig) * BPITCH + c]);
                    bfr[ni][1] = __float_as_uint(Bs[(ks + tig + 4) * BPITCH + c]);
                } else {
                    float2 bv = *(const float2*)(Bs + c * BPITCH + ks + tig * 2);
                    bfr[ni][0] = __float_as_uint(bv.x);
                    bfr[ni][1] = __float_as_uint(bv.y);
                }
            }
            #pragma unroll
            for (int mi = 0; mi < 4; mi++)
                #pragma unroll
                for (int ni = 0; ni < 4; ni++)
                    mma_tf32(acc[mi][ni], afr[mi], bfr[ni]);
        }
        __syncthreads();
    }

    // ------------------------------ epilogue ---------------------------------
    #pragma unroll
    for (int mi = 0; mi < 4; mi++) {
        #pragma unroll
        for (int half = 0; half < 2; half++) {
            int m = m0 + mw + mi * 16 + grp + half * 8;
            #pragma unroll
            for (int ni = 0; ni < 4; ni++) {
                int n = n0 + nw + ni * 8 + tig * 2;
                float v0 = acc[mi][ni][half * 2 + 0];
                float v1 = acc[mi][ni][half * 2 + 1];
                if (EPI == 0) {
                    v0 += a0[n];     v1 += a0[n + 1];
                    v0 = v0 / (1.0f + __expf(-v0));
                    v1 = v1 / (1.0f + __expf(-v1));
                    if (n < HIDV)     v0 = tf32r(v0);
                    if (n + 1 < HIDV) v1 = tf32r(v1);
                    *(float2*)(C + (size_t)m * ldc + n) = make_float2(v0, v1);
                } else if (EPI == 1) {
                    float t0 = fmaxf(v0 * scale, 0.0f);
                    float t1 = fmaxf(v1 * scale, 0.0f);
                    C[quad_off(m, n,     LSEQ / 8)] = tf32r(t0 * t0);
                    C[quad_off(m, n + 1, LSEQ / 8)] = tf32r(t1 * t1);
                } else if (EPI == 2) {
                    v0 *= ax[(size_t)m * ldaux + n];
                    v1 *= ax[(size_t)m * ldaux + n + 1];
                    *(float2*)(C + (size_t)m * ldc + n) = make_float2(v0, v1);
                } else {            // EPI 3: fused Z -> q (quad), k (perm)
                    v0 += a0[n];     v1 += a0[n + 1];
                    v0 = v0 / (1.0f + __expf(-v0));
                    v1 = v1 / (1.0f + __expf(-v1));
                    C0[quad_off(m, n,     QKD / 8)] = tf32r(v0 * a1[n]     + a2[n]);
                    C0[quad_off(m, n + 1, QKD / 8)] = tf32r(v1 * a1[n + 1] + a2[n + 1]);
                    C1[(size_t)m * QKD + kperm(n)]     = tf32r(v0 * a1[QKD + n]     + a2[QKD + n]);
                    C1[(size_t)m * QKD + kperm(n + 1)] = tf32r(v1 * a1[QKD + n + 1] + a2[QKD + n + 1]);
                }
            }
        }
    }
}

// ------------------------- output projection (1024 -> 8) ---------------------
__global__ void out_kernel(const float* __restrict__ Vg, const float* __restrict__ Wo,
                           const float* __restrict__ bo, float* __restrict__ out) {
    int row  = blockIdx.x * (blockDim.x >> 5) + (threadIdx.x >> 5);
    int lane = threadIdx.x & 31;
    const float* vr = Vg + (size_t)row * HIDV;
    float acc[OUTD];
    #pragma unroll
    for (int o = 0; o < OUTD; o++) acc[o] = 0.0f;
    for (int kk = lane; kk < HIDV; kk += 32) {
        float v = vr[kk];
        const float* w = Wo + (size_t)kk * OUTD;
        #pragma unroll
        for (int o = 0; o < OUTD; o++) acc[o] += v * w[o];
    }
    #pragma unroll
    for (int o = 0; o < OUTD; o++) {
        #pragma unroll
        for (int off = 16; off; off >>= 1)
            acc[o] += __shfl_xor_sync(0xffffffffu, acc[o], off);
    }
    if (lane < OUTD) out[(size_t)row * OUTD + lane] = acc[lane] + bo[lane];
}

// --------------------------------- launch ------------------------------------
extern "C" void kernel_launch(void* const* d_in, const int* in_sizes, int n_in,
                              void* d_out, int out_size) {
    const float* x     = (const float*)d_in[0];
    const float* ln_g  = (const float*)d_in[1];
    const float* ln_b  = (const float*)d_in[2];
    const float* Wh    = (const float*)d_in[3];
    const float* bh    = (const float*)d_in[4];
    const float* Wqk   = (const float*)d_in[5];
    const float* bqk   = (const float*)d_in[6];
    const float* gamma = (const float*)d_in[7];
    const float* beta  = (const float*)d_in[8];
    const float* Wo    = (const float*)d_in[9];
    const float* bo    = (const float*)d_in[10];
    float* out = (float*)d_out;

    float *normed, *WhR, *WqkR, *hidden, *q, *k, *A, *V;
    cudaGetSymbolAddress((void**)&normed, g_normed);
    cudaGetSymbolAddress((void**)&WhR,    g_WhR);
    cudaGetSymbolAddress((void**)&WqkR,   g_WqkR);
    cudaGetSymbolAddress((void**)&hidden, g_hidden);
    cudaGetSymbolAddress((void**)&q,      g_q);
    cudaGetSymbolAddress((void**)&k,      g_k);
    cudaGetSymbolAddress((void**)&A,      g_A);
    cudaGetSymbolAddress((void**)&V,      g_V);

    // smem: A 2*4096*4 = 32768 B; B BL0 2*4352*4 = 34816 B; BL1 2*5120*4 = 40960 B
    const int SM_B0 = 32768 + 34816;   // 67584
    const int SM_B1 = 32768 + 40960;   // 73728
    static bool attr_done = false;
    if (!attr_done) {
        cudaFuncSetAttribute(tgemm<0,0>, cudaFuncAttributeMaxDynamicSharedMemorySize, SM_B0);
        cudaFuncSetAttribute(tgemm<3,0>, cudaFuncAttributeMaxDynamicSharedMemorySize, SM_B0);
        cudaFuncSetAttribute(tgemm<1,1>, cudaFuncAttributeMaxDynamicSharedMemorySize, SM_B1);
        cudaFuncSetAttribute(tgemm<2,0>, cudaFuncAttributeMaxDynamicSharedMemorySize, SM_B0);
        attr_done = true;
    }

    // 0. tf32-round the weights (row-major, unchanged layout)
    round_tf32<<<(DIMV * HID2 + 255) / 256, 256>>>(Wh,  WhR,  DIMV * HID2);
    round_tf32<<<(DIMV * QKD  + 255) / 256, 256>>>(Wqk, WqkR, DIMV * QKD);

    // 1. LayerNorm -> normed (quad layout, tf32)
    ln_kernel<<<ROWS, 128>>>(x, ln_g, ln_b, normed);

    // 2. hidden = silu(normed @ Wh + bh)   [16384, 2048]
    tgemm<0,0><<<dim3(HID2 / 128, ROWS / 128, 1), 256, SM_B0>>>(
        normed, DIMV / 8, 0, WhR, HID2, 0, hidden, nullptr,
        DIMV, HID2, 0, bh, nullptr, nullptr, 0, 0, 0.0f);

    // 3. Z GEMM with fused silu + q/k affine  -> q (quad), k (perm)
    tgemm<3,0><<<dim3(1, ROWS / 128, 1), 256, SM_B0>>>(
        normed, DIMV / 8, 0, WqkR, QKD, 0, q, k,
        DIMV, QKD, 0, bqk, gamma, beta, 0, 0, 0.0f);

    // 4. A = tf32(relu(q @ k^T / L)^2) per batch -> quad layout
    tgemm<1,1><<<dim3(LSEQ / 128, LSEQ / 128, NB), 256, SM_B1>>>(
        q, QKD / 8, (size_t)LSEQ * QKD, k, QKD, (size_t)LSEQ * QKD,
        A, nullptr, QKD, 0, (size_t)LSEQ * LSEQ,
        nullptr, nullptr, nullptr, 0, 0, 1.0f / LSEQ);

    // 5. V = (A @ v) * gate per batch
    tgemm<2,0><<<dim3(HIDV / 128, LSEQ / 128, NB), 256, SM_B0>>>(
        A, LSEQ / 8, (size_t)LSEQ * LSEQ, hidden, HID2, (size_t)LSEQ * HID2,
        V, nullptr, LSEQ, HIDV, (size_t)LSEQ * HIDV,
        hidden + HIDV, nullptr, nullptr, HID2, (size_t)LSEQ * HID2, 0.0f);

    // 6. out = V @ Wo + bo
    out_kernel<<<ROWS / 8, 256>>>(V, Wo, bo, out);
}

// round 9
// speedup vs baseline: 1.0809x; 1.0084x over previous
#include <cuda_runtime.h>
#include <cstdint>

// Problem constants
#define NB     4
#define LSEQ   4096
#define ROWS   16384
#define DIMV   512
#define HID2   2048
#define HIDV   1024
#define QKD    128
#define OUTD   8

// ------------------------- scratch (static device globals) -------------------
__device__ float g_normed[(size_t)ROWS * DIMV];      // quad layout, tf32
__device__ float g_WhR   [(size_t)DIMV * HID2];      // row-major [k][n], tf32
__device__ float g_WqkR  [(size_t)DIMV * QKD];       // row-major [k][n], tf32
__device__ float g_hidden[(size_t)ROWS * HID2];      // [m][2048]: v tf32 | gate fp32
__device__ float g_q     [(size_t)ROWS * QKD];       // quad layout, tf32
__device__ float g_k     [(size_t)ROWS * QKD];       // row-major, k-pair-permuted, tf32
__device__ float g_A     [(size_t)NB * LSEQ * LSEQ]; // quad layout per batch, tf32
__device__ float g_V     [(size_t)ROWS * HIDV];      // [m][1024]

// ------------------------------ helpers --------------------------------------
__device__ __forceinline__ uint32_t f2tf32(float f) {
    uint32_t r;
    asm("cvt.rna.tf32.f32 %0, %1;" : "=r"(r) : "f"(f));
    return r;
}
__device__ __forceinline__ float tf32r(float f) { return __uint_as_float(f2tf32(f)); }

__device__ __forceinline__ uint32_t smem_u32(const void* p) {
    uint32_t a;
    asm("{ .reg .u64 t; cvta.to.shared.u64 t, %1; cvt.u32.u64 %0, t; }" : "=r"(a) : "l"(p));
    return a;
}
__device__ __forceinline__ void cp16(uint32_t s, const float* g) {
    asm volatile("cp.async.cg.shared.global [%0], [%1], 16;" :: "r"(s), "l"(g));
}
#define CP_COMMIT() asm volatile("cp.async.commit_group;" ::: "memory")
#define CP_WAIT0()  asm volatile("cp.async.wait_group 0;" ::: "memory")
#define CP_WAIT1()  asm volatile("cp.async.wait_group 1;" ::: "memory")

__device__ __forceinline__ void mma_tf32(float* c, const uint32_t* a, const uint32_t* b) {
    asm volatile(
        "mma.sync.aligned.m16n8k8.row.col.f32.tf32.tf32.f32 "
        "{%0,%1,%2,%3},{%4,%5,%6,%7},{%8,%9},{%0,%1,%2,%3};"
        : "+f"(c[0]), "+f"(c[1]), "+f"(c[2]), "+f"(c[3])
        : "r"(a[0]), "r"(a[1]), "r"(a[2]), "r"(a[3]), "r"(b[0]), "r"(b[1]));
}

// Quad layout: X[M][K] -> blocks of 16 rows x 8 cols (128 floats); within a
// block, element (m,k) at ((m&7)*4 + (k&3))*4 + ((k>>2)&1)*2 + ((m>>3)&1).
// A thread's m16n8k8 A-fragment is one contiguous 16B quad.
__device__ __forceinline__ size_t quad_off(int m, int k, int K8) {
    return ((size_t)(m >> 4) * K8 + (k >> 3)) * 128
         + (size_t)(((m & 7) * 4 + (k & 3)) * 4 + ((k >> 2) & 1) * 2 + ((m >> 3) & 1));
}
// k-pair permutation within 8-groups: [0,4,1,5,2,6,3,7]
__device__ __forceinline__ int kperm(int k) {
    return (k & ~7) + (k & 3) * 2 + ((k >> 2) & 1);
}

// ------------------------------ LayerNorm (quad tf32 out) --------------------
__global__ void ln_kernel(const float* __restrict__ x, const float* __restrict__ g,
                          const float* __restrict__ b, float* __restrict__ o) {
    int row = blockIdx.x;
    int t = threadIdx.x;
    const float4* xr = (const float4*)(x + (size_t)row * DIMV);
    float4 xv = xr[t];
    float s  = xv.x + xv.y + xv.z + xv.w;
    float ss = xv.x*xv.x + xv.y*xv.y + xv.z*xv.z + xv.w*xv.w;
    #pragma unroll
    for (int off = 16; off; off >>= 1) {
        s  += __shfl_xor_sync(0xffffffffu, s,  off);
        ss += __shfl_xor_sync(0xffffffffu, ss, off);
    }
    __shared__ float sh_s[4], sh_ss[4];
    if ((t & 31) == 0) { sh_s[t >> 5] = s; sh_ss[t >> 5] = ss; }
    __syncthreads();
    s  = sh_s[0] + sh_s[1] + sh_s[2] + sh_s[3];
    ss = sh_ss[0] + sh_ss[1] + sh_ss[2] + sh_ss[3];
    float mu  = s * (1.0f / DIMV);
    float var = ss * (1.0f / DIMV) - mu * mu;
    float inv = rsqrtf(var + 1e-5f);
    float4 gv = ((const float4*)g)[t];
    float4 bv = ((const float4*)b)[t];
    float r0 = tf32r((xv.x - mu) * inv * gv.x + bv.x);
    float r1 = tf32r((xv.y - mu) * inv * gv.y + bv.y);
    float r2 = tf32r((xv.z - mu) * inv * gv.z + bv.z);
    float r3 = tf32r((xv.w - mu) * inv * gv.w + bv.w);
    int d0 = t * 4;
    o[quad_off(row, d0 + 0, DIMV / 8)] = r0;
    o[quad_off(row, d0 + 1, DIMV / 8)] = r1;
    o[quad_off(row, d0 + 2, DIMV / 8)] = r2;
    o[quad_off(row, d0 + 3, DIMV / 8)] = r3;
}

// --------------------------- tf32 rounding copy ------------------------------
__global__ void round_tf32(const float* __restrict__ s, float* __restrict__ d, int n) {
    int i = blockIdx.x * blockDim.x + threadIdx.x;
    if (i < n) d[i] = tf32r(s[i]);
}

// --------------------------- tf32 tensor-core GEMM ---------------------------
// D[m][n] = sum_k A[m][k]*B-op;  A in quad layout (LDS.128 frags).
// BL=0: B row-major [K][N] (pitch 136, 2x LDS.32 frags)
// BL=1: B row-major [N][K] k-pair-permuted (pitch 40, LDS.64 frags)
// CTA 128x128, BK=32, 3-stage cp.async pipeline, ONE barrier per iteration.
// 8 warps, warp tile 64x32.
// EPI 0 (Wh):  v = silu(acc+a0[n]); tf32 when n<HIDV (v half); raw (gate) else
// EPI 1 (qkT): A-out quad = tf32(relu(acc*scale)^2)
// EPI 2 (AV):  V = acc * a0[m*ldaux+n]
// EPI 3 (Z):   s = silu(acc+a0[n]); q quad = tf32(s*a1[n]+a2[n]);
//              k perm = tf32(s*a1[128+n]+a2[128+n])
template<int EPI, int BL>
__global__ void __launch_bounds__(256, 2)
tgemm(const float* __restrict__ Ag, int K8, size_t sA,
      const float* __restrict__ Bg, int ldb, size_t sB,
      float* __restrict__ C0, float* __restrict__ C1,
      int K, int ldc, size_t sC,
      const float* __restrict__ a0, const float* __restrict__ a1,
      const float* __restrict__ a2, int ldaux, size_t sAux, float scale)
{
    constexpr int ASTG = 4096;                 // floats per A stage (32 blocks x 128)
    constexpr int BPITCH = BL ? 40 : 136;
    constexpr int BSTG = BL ? (128 * 40) : (32 * 136);
    constexpr int NSTAGE = 3;

    extern __shared__ float sm[];
    float* AsBase = sm;
    float* BsBase = sm + NSTAGE * ASTG;
    const uint32_t sbA = smem_u32(AsBase);
    const uint32_t sbB = smem_u32(BsBase);

    const float* A = Ag + blockIdx.z * sA;
    const float* B = Bg + blockIdx.z * sB;
    float*       C = C0 + blockIdx.z * sC;
    const float* ax = a0 + blockIdx.z * sAux;

    const int tid  = threadIdx.x;
    const int warp = tid >> 5;
    const int lane = tid & 31;
    const int grp  = lane >> 2;
    const int tig  = lane & 3;
    const int mw   = (warp >> 2) * 64;   // 0, 64
    const int nw   = (warp & 3) * 32;    // 0, 32, 64, 96
    const int m0 = blockIdx.y * 128, n0 = blockIdx.x * 128;
    const int mbb = (mw >> 4);           // 0 or 4: warp's base m-block

    float acc[4][4][4];
    #pragma unroll
    for (int mi = 0; mi < 4; mi++)
        #pragma unroll
        for (int ni = 0; ni < 4; ni++)
            #pragma unroll
            for (int r = 0; r < 4; r++) acc[mi][ni][r] = 0.0f;

    auto load_stage = [&](int st, int k0) {
        // A: 32 quad-blocks x 128 floats = 1024 chunks, 4/thread
        #pragma unroll
        for (int l = 0; l < 4; l++) {
            int qc = tid + l * 256;
            int blk = qc >> 5, c = qc & 31;
            int mbl = blk >> 2, kbl = blk & 3;
            size_t gblk = (size_t)(m0 / 16 + mbl) * K8 + (k0 / 8 + kbl);
            cp16(sbA + (uint32_t)(st * ASTG + blk * 128 + c * 4) * 4,
                 A + gblk * 128 + c * 4);
        }
        #pragma unroll
        for (int l = 0; l < 4; l++) {
            int fid = tid + l * 256;
            if (BL == 0) {   // 32 rows x 128 floats
                int r = fid >> 5, ch = fid & 31;
                cp16(sbB + (uint32_t)(st * BSTG + r * BPITCH + ch * 4) * 4,
                     B + (size_t)(k0 + r) * ldb + n0 + ch * 4);
            } else {         // 128 rows x 32 floats (perm within rows is opaque)
                int r = fid >> 3, ch = fid & 7;
                cp16(sbB + (uint32_t)(st * BSTG + r * BPITCH + ch * 4) * 4,
                     B + (size_t)(n0 + r) * ldb + k0 + ch * 4);
            }
        }
        CP_COMMIT();
    };

    const int niter = K / 32;
    // prologue: stages 0 and 1 in flight
    load_stage(0, 0);
    if (niter > 1) load_stage(1, 32);

    for (int it = 0; it < niter; it++) {
        if (it + 1 < niter) { CP_WAIT1(); }   // stage `it` landed, `it+1` may fly
        else                { CP_WAIT0(); }
        __syncthreads();                       // ONE barrier per iteration
        if (it + 2 < niter) load_stage((it + 2) % NSTAGE, (it + 2) * 32);

        const float* As = AsBase + (it % NSTAGE) * ASTG;
        const float* Bs = BsBase + (it % NSTAGE) * BSTG;

        #pragma unroll
        for (int ks = 0; ks < 32; ks += 8) {
            uint32_t afr[4][4], bfr[4][2];
            #pragma unroll
            for (int mi = 0; mi < 4; mi++) {
                float4 av = *(const float4*)(As + ((mbb + mi) * 4 + (ks >> 3)) * 128
                                                + (grp * 4 + tig) * 4);
                afr[mi][0] = __float_as_uint(av.x);
                afr[mi][1] = __float_as_uint(av.y);
                afr[mi][2] = __float_as_uint(av.z);
                afr[mi][3] = __float_as_uint(av.w);
            }
            #pragma unroll
            for (int ni = 0; ni < 4; ni++) {
                int c = nw + ni * 8 + grp;
                if (BL == 0) {
                    bfr[ni][0] = __float_as_uint(Bs[(ks + tig) * BPITCH + c]);
                    bfr[ni][1] = __float_as_uint(Bs[(ks + tig + 4) * BPITCH + c]);
                } else {
                    float2 bv = *(const float2*)(Bs + c * BPITCH + ks + tig * 2);
                    bfr[ni][0] = __float_as_uint(bv.x);
                    bfr[ni][1] = __float_as_uint(bv.y);
                }
            }
            #pragma unroll
            for (int mi = 0; mi < 4; mi++)
                #pragma unroll
                for (int ni = 0; ni < 4; ni++)
                    mma_tf32(acc[mi][ni], afr[mi], bfr[ni]);
        }
    }
    __syncthreads();

    // ------------------------------ epilogue ---------------------------------
    #pragma unroll
    for (int mi = 0; mi < 4; mi++) {
        #pragma unroll
        for (int half = 0; half < 2; half++) {
            int m = m0 + mw + mi * 16 + grp + half * 8;
            #pragma unroll
            for (int ni = 0; ni < 4; ni++) {
                int n = n0 + nw + ni * 8 + tig * 2;
                float v0 = acc[mi][ni][half * 2 + 0];
                float v1 = acc[mi][ni][half * 2 + 1];
                if (EPI == 0) {
                    v0 += a0[n];     v1 += a0[n + 1];
                    v0 = v0 / (1.0f + __expf(-v0));
                    v1 = v1 / (1.0f + __expf(-v1));
                    if (n < HIDV)     v0 = tf32r(v0);
                    if (n + 1 < HIDV) v1 = tf32r(v1);
                    *(float2*)(C + (size_t)m * ldc + n) = make_float2(v0, v1);
                } else if (EPI == 1) {
                    float t0 = fmaxf(v0 * scale, 0.0f);
                    float t1 = fmaxf(v1 * scale, 0.0f);
                    C[quad_off(m, n,     LSEQ / 8)] = tf32r(t0 * t0);
                    C[quad_off(m, n + 1, LSEQ / 8)] = tf32r(t1 * t1);
                } else if (EPI == 2) {
                    v0 *= ax[(size_t)m * ldaux + n];
                    v1 *= ax[(size_t)m * ldaux + n + 1];
                    *(float2*)(C + (size_t)m * ldc + n) = make_float2(v0, v1);
                } else {            // EPI 3: fused Z -> q (quad), k (perm)
                    v0 += a0[n];     v1 += a0[n + 1];
                    v0 = v0 / (1.0f + __expf(-v0));
                    v1 = v1 / (1.0f + __expf(-v1));
                    C0[quad_off(m, n,     QKD / 8)] = tf32r(v0 * a1[n]     + a2[n]);
                    C0[quad_off(m, n + 1, QKD / 8)] = tf32r(v1 * a1[n + 1] + a2[n + 1]);
                    C1[(size_t)m * QKD + kperm(n)]     = tf32r(v0 * a1[QKD + n]     + a2[QKD + n]);
                    C1[(size_t)m * QKD + kperm(n + 1)] = tf32r(v1 * a1[QKD + n + 1] + a2[QKD + n + 1]);
                }
            }
        }
    }
}

// ------------------------- output projection (1024 -> 8) ---------------------
__global__ void out_kernel(const float* __restrict__ Vg, const float* __restrict__ Wo,
                           const float* __restrict__ bo, float* __restrict__ out) {
    int row  = blockIdx.x * (blockDim.x >> 5) + (threadIdx.x >> 5);
    int lane = threadIdx.x & 31;
    const float* vr = Vg + (size_t)row * HIDV;
    float acc[OUTD];
    #pragma unroll
    for (int o = 0; o < OUTD; o++) acc[o] = 0.0f;
    for (int kk = lane; kk < HIDV; kk += 32) {
        float v = vr[kk];
        const float* w = Wo + (size_t)kk * OUTD;
        #pragma unroll
        for (int o = 0; o < OUTD; o++) acc[o] += v * w[o];
    }
    #pragma unroll
    for (int o = 0; o < OUTD; o++) {
        #pragma unroll
        for (int off = 16; off; off >>= 1)
            acc[o] += __shfl_xor_sync(0xffffffffu, acc[o], off);
    }
    if (lane < OUTD) out[(size_t)row * OUTD + lane] = acc[lane] + bo[lane];
}

// --------------------------------- launch ------------------------------------
extern "C" void kernel_launch(void* const* d_in, const int* in_sizes, int n_in,
                              void* d_out, int out_size) {
    const float* x     = (const float*)d_in[0];
    const float* ln_g  = (const float*)d_in[1];
    const float* ln_b  = (const float*)d_in[2];
    const float* Wh    = (const float*)d_in[3];
    const float* bh    = (const float*)d_in[4];
    const float* Wqk   = (const float*)d_in[5];
    const float* bqk   = (const float*)d_in[6];
    const float* gamma = (const float*)d_in[7];
    const float* beta  = (const float*)d_in[8];
    const float* Wo    = (const float*)d_in[9];
    const float* bo    = (const float*)d_in[10];
    float* out = (float*)d_out;

    float *normed, *WhR, *WqkR, *hidden, *q, *k, *A, *V;
    cudaGetSymbolAddress((void**)&normed, g_normed);
    cudaGetSymbolAddress((void**)&WhR,    g_WhR);
    cudaGetSymbolAddress((void**)&WqkR,   g_WqkR);
    cudaGetSymbolAddress((void**)&hidden, g_hidden);
    cudaGetSymbolAddress((void**)&q,      g_q);
    cudaGetSymbolAddress((void**)&k,      g_k);
    cudaGetSymbolAddress((void**)&A,      g_A);
    cudaGetSymbolAddress((void**)&V,      g_V);

    // smem (3 stages): A 3*4096*4 = 49152 B; B BL0 3*4352*4 = 52224 B; BL1 3*5120*4 = 61440 B
    const int SM_B0 = 49152 + 52224;   // 101376
    const int SM_B1 = 49152 + 61440;   // 110592
    static bool attr_done = false;
    if (!attr_done) {
        cudaFuncSetAttribute(tgemm<0,0>, cudaFuncAttributeMaxDynamicSharedMemorySize, SM_B0);
        cudaFuncSetAttribute(tgemm<3,0>, cudaFuncAttributeMaxDynamicSharedMemorySize, SM_B0);
        cudaFuncSetAttribute(tgemm<1,1>, cudaFuncAttributeMaxDynamicSharedMemorySize, SM_B1);
        cudaFuncSetAttribute(tgemm<2,0>, cudaFuncAttributeMaxDynamicSharedMemorySize, SM_B0);
        attr_done = true;
    }

    // 0. tf32-round the weights (row-major, unchanged layout)
    round_tf32<<<(DIMV * HID2 + 255) / 256, 256>>>(Wh,  WhR,  DIMV * HID2);
    round_tf32<<<(DIMV * QKD  + 255) / 256, 256>>>(Wqk, WqkR, DIMV * QKD);

    // 1. LayerNorm -> normed (quad layout, tf32)
    ln_kernel<<<ROWS, 128>>>(x, ln_g, ln_b, normed);

    // 2. hidden = silu(normed @ Wh + bh)   [16384, 2048]
    tgemm<0,0><<<dim3(HID2 / 128, ROWS / 128, 1), 256, SM_B0>>>(
        normed, DIMV / 8, 0, WhR, HID2, 0, hidden, nullptr,
        DIMV, HID2, 0, bh, nullptr, nullptr, 0, 0, 0.0f);

    // 3. Z GEMM with fused silu + q/k affine  -> q (quad), k (perm)
    tgemm<3,0><<<dim3(1, ROWS / 128, 1), 256, SM_B0>>>(
        normed, DIMV / 8, 0, WqkR, QKD, 0, q, k,
        DIMV, QKD, 0, bqk, gamma, beta, 0, 0, 0.0f);

    // 4. A = tf32(relu(q @ k^T / L)^2) per batch -> quad layout
    tgemm<1,1><<<dim3(LSEQ / 128, LSEQ / 128, NB), 256, SM_B1>>>(
        q, QKD / 8, (size_t)LSEQ * QKD, k, QKD, (size_t)LSEQ * QKD,
        A, nullptr, QKD, 0, (size_t)LSEQ * LSEQ,
        nullptr, nullptr, nullptr, 0, 0, 1.0f / LSEQ);

    // 5. V = (A @ v) * gate per batch
    tgemm<2,0><<<dim3(HIDV / 128, LSEQ / 128, NB), 256, SM_B0>>>(
        A, LSEQ / 8, (size_t)LSEQ * LSEQ, hidden, HID2, (size_t)LSEQ * HID2,
        V, nullptr, LSEQ, HIDV, (size_t)LSEQ * HIDV,
        hidden + HIDV, nullptr, nullptr, HID2, (size_t)LSEQ * HID2, 0.0f);

    // 6. out = V @ Wo + bo
    out_kernel<<<ROWS / 8, 256>>>(V, Wo, bo, out);
}

// round 10
// speedup vs baseline: 1.7731x; 1.6404x over previous
#include <cuda_runtime.h>
#include <cuda_fp16.h>
#include <cstdint>

// Problem constants
#define NB     4
#define LSEQ   4096
#define ROWS   16384
#define DIMV   512
#define HID2   2048
#define HIDV   1024
#define QKD    128
#define OUTD   8

#define A_SCALE 1099511627776.0f        // 2^40  (exact)
#define A_INV   9.094947017729282e-13f  // 2^-40 (exact)

// ------------------------- scratch (static device globals) -------------------
__device__ __half g_normed[(size_t)ROWS * DIMV];     // quad16 layout
__device__ __half g_Wh16 [(size_t)DIMV * HID2];      // pair layout [k/2][n][2]
__device__ __half g_Wqk16[(size_t)DIMV * QKD];       // pair layout
__device__ __half g_v16  [(size_t)ROWS * HIDV];      // pair layout (rows = tokens)
__device__ float  g_gate [(size_t)ROWS * HIDV];      // fp32
__device__ __half g_q16  [(size_t)ROWS * QKD];       // quad16 layout
__device__ __half g_k16  [(size_t)ROWS * QKD];       // plain [token][128]
__device__ __half g_A16  [(size_t)NB * LSEQ * LSEQ]; // quad16 per batch (xA_SCALE)
__device__ float  g_V    [(size_t)ROWS * HIDV];      // fp32

// ------------------------------ helpers --------------------------------------
__device__ __forceinline__ uint32_t smem_u32(const void* p) {
    uint32_t a;
    asm("{ .reg .u64 t; cvta.to.shared.u64 t, %1; cvt.u32.u64 %0, t; }" : "=r"(a) : "l"(p));
    return a;
}
__device__ __forceinline__ void cp16(uint32_t s, const void* g) {
    asm volatile("cp.async.cg.shared.global [%0], [%1], 16;" :: "r"(s), "l"(g));
}
#define CP_COMMIT() asm volatile("cp.async.commit_group;" ::: "memory")
#define CP_WAIT0()  asm volatile("cp.async.wait_group 0;" ::: "memory")
#define CP_WAIT1()  asm volatile("cp.async.wait_group 1;" ::: "memory")

__device__ __forceinline__ void mma_f16(float* c, const uint32_t* a, const uint32_t* b) {
    asm volatile(
        "mma.sync.aligned.m16n8k16.row.col.f32.f16.f16.f32 "
        "{%0,%1,%2,%3},{%4,%5,%6,%7},{%8,%9},{%0,%1,%2,%3};"
        : "+f"(c[0]), "+f"(c[1]), "+f"(c[2]), "+f"(c[3])
        : "r"(a[0]), "r"(a[1]), "r"(a[2]), "r"(a[3]), "r"(b[0]), "r"(b[1]));
}

// quad16 A-layout: 16m x 16k blocks of 256 halves; a thread's m16n8k16 A
// fragment (8 halves) is contiguous (1 LDS.128).
__device__ __forceinline__ size_t q16_off(int m, int k, int K16) {
    return ((size_t)(m >> 4) * K16 + (k >> 4)) * 256
         + (size_t)((((m & 7) << 2) + ((k & 7) >> 1)) * 8
                    + ((k >> 3) & 1) * 4 + ((m >> 3) & 1) * 2 + (k & 1));
}
__device__ __forceinline__ uint32_t packh2(float a, float b) {
    __half2 h = __floats2half2_rn(a, b);
    return *(uint32_t*)&h;
}

// ------------------------------ LayerNorm (quad16 fp16 out) ------------------
__global__ void ln_kernel(const float* __restrict__ x, const float* __restrict__ g,
                          const float* __restrict__ b, __half* __restrict__ o) {
    int row = blockIdx.x;
    int t = threadIdx.x;
    const float4* xr = (const float4*)(x + (size_t)row * DIMV);
    float4 xv = xr[t];
    float s  = xv.x + xv.y + xv.z + xv.w;
    float ss = xv.x*xv.x + xv.y*xv.y + xv.z*xv.z + xv.w*xv.w;
    #pragma unroll
    for (int off = 16; off; off >>= 1) {
        s  += __shfl_xor_sync(0xffffffffu, s,  off);
        ss += __shfl_xor_sync(0xffffffffu, ss, off);
    }
    __shared__ float sh_s[4], sh_ss[4];
    if ((t & 31) == 0) { sh_s[t >> 5] = s; sh_ss[t >> 5] = ss; }
    __syncthreads();
    s  = sh_s[0] + sh_s[1] + sh_s[2] + sh_s[3];
    ss = sh_ss[0] + sh_ss[1] + sh_ss[2] + sh_ss[3];
    float mu  = s * (1.0f / DIMV);
    float var = ss * (1.0f / DIMV) - mu * mu;
    float inv = rsqrtf(var + 1e-5f);
    float4 gv = ((const float4*)g)[t];
    float4 bv = ((const float4*)b)[t];
    float r0 = (xv.x - mu) * inv * gv.x + bv.x;
    float r1 = (xv.y - mu) * inv * gv.y + bv.y;
    float r2 = (xv.z - mu) * inv * gv.z + bv.z;
    float r3 = (xv.w - mu) * inv * gv.w + bv.w;
    int d0 = t * 4;
    *(uint32_t*)(o + q16_off(row, d0,     DIMV / 16)) = packh2(r0, r1);
    *(uint32_t*)(o + q16_off(row, d0 + 2, DIMV / 16)) = packh2(r2, r3);
}

// --------------------- weight fp16 conversion to pair layout -----------------
__global__ void round16_pair(const float* __restrict__ s, __half* __restrict__ d,
                             int K, int N) {
    int i = blockIdx.x * blockDim.x + threadIdx.x;
    if (i >= K * N) return;
    int k = i / N, n = i - k * N;
    d[(size_t)(k >> 1) * (2 * N) + n * 2 + (k & 1)] = __float2half_rn(s[i]);
}

// --------------------------- fp16 tensor-core GEMM ---------------------------
// D[m][n] = sum_k A[m][k]*B[k][n];  A quad16 (LDS.128 frags), acc fp32.
// BL=0: B pair layout [k/2][n][2] (word per n), smem pitch 136 words
// BL=1: B plain [token n][128 k halves], smem pitch 68 words (qkT)
// CTA 128x128, 8 warps, warp tile 64x32. NST=3: one barrier/iter pipeline.
// NST=1 (qkT, K=BK=128): single stage, no pipeline.
// EPI 0 (Wh): s=silu(acc+a0[n]); n<HIDV -> v16 pair; else gate fp32
// EPI 1 (qkT): A16 quad16 = fp16(relu(acc*scale)^2 * A_SCALE)
// EPI 2 (AV): V = acc * A_INV * gate[(z*4096+m)*HIDV+n]
// EPI 3 (Z):  s=silu(acc+a0[n]); q16 quad16 = s*a1[n]+a2[n];
//             k16[m][n] = s*a1[128+n]+a2[128+n]
template<int EPI, int BL, int BK, int NST>
__global__ void __launch_bounds__(256, 2)
tgemm(const __half* __restrict__ Ag, int K16g, size_t sA,
      const uint32_t* __restrict__ Bw, int ldbw, size_t sBw,
      void* __restrict__ C0, void* __restrict__ C1,
      int K,
      const float* __restrict__ a0, const float* __restrict__ a1,
      const float* __restrict__ a2, size_t sAux, float scale)
{
    constexpr int KB16   = BK / 16;
    constexpr int ASTG_W = 64 * BK;                    // words per A stage
    constexpr int BSTG_W = BL ? (128 * 68) : ((BK / 2) * 136);

    extern __shared__ uint32_t smw[];
    uint32_t* Asw = smw;
    uint32_t* Bsw = smw + NST * ASTG_W;
    const uint32_t sbA = smem_u32(Asw);
    const uint32_t sbB = smem_u32(Bsw);

    const int z = blockIdx.z;
    const __half*    A = Ag + z * sA;
    const uint32_t*  B = Bw + z * sBw;
    const float*    ax = a0 + z * sAux;

    const int tid  = threadIdx.x;
    const int warp = tid >> 5;
    const int lane = tid & 31;
    const int grp  = lane >> 2;
    const int tig  = lane & 3;
    const int mw   = (warp >> 2) * 64;
    const int nw   = (warp & 3) * 32;
    const int m0 = blockIdx.y * 128, n0 = blockIdx.x * 128;
    const int mbb = (mw >> 4);

    float acc[4][4][4];
    #pragma unroll
    for (int mi = 0; mi < 4; mi++)
        #pragma unroll
        for (int ni = 0; ni < 4; ni++)
            #pragma unroll
            for (int r = 0; r < 4; r++) acc[mi][ni][r] = 0.0f;

    auto load_stage = [&](int st, int k0) {
        // A: 8 m-blocks x KB16 k-blocks x 512B; 16*BK chunks
        #pragma unroll
        for (int l = 0; l < 16 * BK / 256; l++) {
            int qc = tid + l * 256;
            int blk = qc >> 5, c = qc & 31;
            int mbl = blk / KB16, kbl = blk - mbl * KB16;
            const __half* gsrc = A + ((size_t)(m0 / 16 + mbl) * K16g + (k0 / 16 + kbl)) * 256 + c * 8;
            cp16(sbA + (uint32_t)(st * ASTG_W + blk * 128 + c * 4) * 4, gsrc);
        }
        if (BL == 0) {   // BK/2 pair rows x 128 words
            #pragma unroll
            for (int l = 0; l < 16 * BK / 256; l++) {
                int id = tid + l * 256;
                int r = id >> 5, c = id & 31;
                cp16(sbB + (uint32_t)(st * BSTG_W + r * 136 + c * 4) * 4,
                     B + ((size_t)(k0 >> 1) + r) * ldbw + n0 + c * 4);
            }
        } else {         // 128 token rows x 16 chunks
            #pragma unroll
            for (int l = 0; l < 8; l++) {
                int id = tid + l * 256;
                int r = id >> 4, c = id & 15;
                cp16(sbB + (uint32_t)(st * BSTG_W + r * 68 + c * 4) * 4,
                     B + (size_t)(n0 + r) * ldbw + c * 4);
            }
        }
        CP_COMMIT();
    };

    auto compute_stage = [&](int st) {
        const uint32_t* As = Asw + st * ASTG_W;
        const uint32_t* Bs = Bsw + st * BSTG_W;
        #pragma unroll
        for (int s = 0; s < KB16; s++) {
            uint32_t afr[4][4], bfr[4][2];
            #pragma unroll
            for (int mi = 0; mi < 4; mi++) {
                uint4 av = *(const uint4*)(As + (((mbb + mi) * KB16 + s) * 128 + lane * 4));
                afr[mi][0] = av.x; afr[mi][1] = av.y; afr[mi][2] = av.z; afr[mi][3] = av.w;
            }
            #pragma unroll
            for (int ni = 0; ni < 4; ni++) {
                int c = nw + ni * 8 + grp;
                if (BL == 0) {
                    bfr[ni][0] = Bs[(s * 8 + tig) * 136 + c];
                    bfr[ni][1] = Bs[(s * 8 + tig + 4) * 136 + c];
                } else {
                    bfr[ni][0] = Bs[c * 68 + s * 8 + tig];
                    bfr[ni][1] = Bs[c * 68 + s * 8 + tig + 4];
                }
            }
            #pragma unroll
            for (int mi = 0; mi < 4; mi++)
                #pragma unroll
                for (int ni = 0; ni < 4; ni++)
                    mma_f16(acc[mi][ni], afr[mi], bfr[ni]);
        }
    };

    const int niter = K / BK;
    if (NST == 1) {
        load_stage(0, 0);
        CP_WAIT0();
        __syncthreads();
        compute_stage(0);
    } else {
        load_stage(0, 0);
        if (niter > 1) load_stage(1, BK);
        for (int it = 0; it < niter; it++) {
            if (it + 1 < niter) { CP_WAIT1(); }
            else                { CP_WAIT0(); }
            __syncthreads();
            if (it + 2 < niter) load_stage((it + 2) % NST, (it + 2) * BK);
            compute_stage(it % NST);
        }
    }
    __syncthreads();

    // ------------------------------ epilogue ---------------------------------
    #pragma unroll
    for (int mi = 0; mi < 4; mi++) {
        #pragma unroll
        for (int half = 0; half < 2; half++) {
            int m = m0 + mw + mi * 16 + grp + half * 8;
            #pragma unroll
            for (int ni = 0; ni < 4; ni++) {
                int n = n0 + nw + ni * 8 + tig * 2;
                float v0 = acc[mi][ni][half * 2 + 0];
                float v1 = acc[mi][ni][half * 2 + 1];
                if (EPI == 0) {
                    v0 += a0[n];     v1 += a0[n + 1];
                    v0 = v0 / (1.0f + __expf(-v0));
                    v1 = v1 / (1.0f + __expf(-v1));
                    if (n < HIDV) {
                        __half* vv = (__half*)C0;
                        size_t o = (size_t)(m >> 1) * (2 * HIDV) + n * 2 + (m & 1);
                        vv[o]     = __float2half_rn(v0);
                        vv[o + 2] = __float2half_rn(v1);
                    } else {
                        float* gb = (float*)C1;
                        *(float2*)(gb + (size_t)m * HIDV + (n - HIDV)) = make_float2(v0, v1);
                    }
                } else if (EPI == 1) {
                    float t0 = fmaxf(v0 * scale, 0.0f);
                    float t1 = fmaxf(v1 * scale, 0.0f);
                    __half* Az = (__half*)C0 + (size_t)z * LSEQ * LSEQ;
                    *(uint32_t*)(Az + q16_off(m, n, LSEQ / 16)) =
                        packh2(t0 * t0 * A_SCALE, t1 * t1 * A_SCALE);
                } else if (EPI == 2) {
                    float* Vp = (float*)C0 + (size_t)z * LSEQ * HIDV;
                    v0 *= A_INV * ax[(size_t)m * HIDV + n];
                    v1 *= A_INV * ax[(size_t)m * HIDV + n + 1];
                    *(float2*)(Vp + (size_t)m * HIDV + n) = make_float2(v0, v1);
                } else {   // EPI 3
                    v0 += a0[n];     v1 += a0[n + 1];
                    v0 = v0 / (1.0f + __expf(-v0));
                    v1 = v1 / (1.0f + __expf(-v1));
                    __half* qb = (__half*)C0;
                    __half* kb = (__half*)C1;
                    *(uint32_t*)(qb + q16_off(m, n, QKD / 16)) =
                        packh2(v0 * a1[n] + a2[n], v1 * a1[n + 1] + a2[n + 1]);
                    *(uint32_t*)(kb + (size_t)m * QKD + n) =
                        packh2(v0 * a1[QKD + n] + a2[QKD + n],
                               v1 * a1[QKD + n + 1] + a2[QKD + n + 1]);
                }
            }
        }
    }
}

// ------------------------- output projection (1024 -> 8) ---------------------
__global__ void out_kernel(const float* __restrict__ Vg, const float* __restrict__ Wo,
                           const float* __restrict__ bo, float* __restrict__ out) {
    int row  = blockIdx.x * (blockDim.x >> 5) + (threadIdx.x >> 5);
    int lane = threadIdx.x & 31;
    const float* vr = Vg + (size_t)row * HIDV;
    float acc[OUTD];
    #pragma unroll
    for (int o = 0; o < OUTD; o++) acc[o] = 0.0f;
    for (int kk = lane; kk < HIDV; kk += 32) {
        float v = vr[kk];
        const float* w = Wo + (size_t)kk * OUTD;
        #pragma unroll
        for (int o = 0; o < OUTD; o++) acc[o] += v * w[o];
    }
    #pragma unroll
    for (int o = 0; o < OUTD; o++) {
        #pragma unroll
        for (int off = 16; off; off >>= 1)
            acc[o] += __shfl_xor_sync(0xffffffffu, acc[o], off);
    }
    if (lane < OUTD) out[(size_t)row * OUTD + lane] = acc[lane] + bo[lane];
}

// --------------------------------- launch ------------------------------------
extern "C" void kernel_launch(void* const* d_in, const int* in_sizes, int n_in,
                              void* d_out, int out_size) {
    const float* x     = (const float*)d_in[0];
    const float* ln_g  = (const float*)d_in[1];
    const float* ln_b  = (const float*)d_in[2];
    const float* Wh    = (const float*)d_in[3];
    const float* bh    = (const float*)d_in[4];
    const float* Wqk   = (const float*)d_in[5];
    const float* bqk   = (const float*)d_in[6];
    const float* gamma = (const float*)d_in[7];
    const float* beta  = (const float*)d_in[8];
    const float* Wo    = (const float*)d_in[9];
    const float* bo    = (const float*)d_in[10];
    float* out = (float*)d_out;

    __half *normed, *Wh16, *Wqk16, *v16, *q16, *k16, *A16;
    float *gate, *V;
    cudaGetSymbolAddress((void**)&normed, g_normed);
    cudaGetSymbolAddress((void**)&Wh16,   g_Wh16);
    cudaGetSymbolAddress((void**)&Wqk16,  g_Wqk16);
    cudaGetSymbolAddress((void**)&v16,    g_v16);
    cudaGetSymbolAddress((void**)&gate,   g_gate);
    cudaGetSymbolAddress((void**)&q16,    g_q16);
    cudaGetSymbolAddress((void**)&k16,    g_k16);
    cudaGetSymbolAddress((void**)&A16,    g_A16);
    cudaGetSymbolAddress((void**)&V,      g_V);

    // smem (words*4B): BK64/NST3: A 3*4096*4=49152, B0 3*4352*4=52224 -> 101376
    //                  BK128/NST1: A 8192*4=32768, B1 8704*4=34816 -> 67584
    const int SM_P = 101376, SM_Q = 67584;
    static bool attr_done = false;
    if (!attr_done) {
        cudaFuncSetAttribute(tgemm<0,0,64,3>,  cudaFuncAttributeMaxDynamicSharedMemorySize, SM_P);
        cudaFuncSetAttribute(tgemm<3,0,64,3>,  cudaFuncAttributeMaxDynamicSharedMemorySize, SM_P);
        cudaFuncSetAttribute(tgemm<1,1,128,1>, cudaFuncAttributeMaxDynamicSharedMemorySize, SM_Q);
        cudaFuncSetAttribute(tgemm<2,0,64,3>,  cudaFuncAttributeMaxDynamicSharedMemorySize, SM_P);
        attr_done = true;
    }

    // 0. weights -> fp16 pair layout
    round16_pair<<<(DIMV * HID2 + 255) / 256, 256>>>(Wh,  Wh16,  DIMV, HID2);
    round16_pair<<<(DIMV * QKD  + 255) / 256, 256>>>(Wqk, Wqk16, DIMV, QKD);

    // 1. LayerNorm -> normed (quad16 fp16)
    ln_kernel<<<ROWS, 128>>>(x, ln_g, ln_b, normed);

    // 2. Wh GEMM: hidden -> v16 (pair) + gate (fp32)
    tgemm<0,0,64,3><<<dim3(HID2 / 128, ROWS / 128, 1), 256, SM_P>>>(
        normed, DIMV / 16, 0, (const uint32_t*)Wh16, HID2, 0,
        v16, gate, DIMV, bh, nullptr, nullptr, 0, 0.0f);

    // 3. Z GEMM fused silu + affine -> q16 (quad16), k16 (plain)
    tgemm<3,0,64,3><<<dim3(1, ROWS / 128, 1), 256, SM_P>>>(
        normed, DIMV / 16, 0, (const uint32_t*)Wqk16, QKD, 0,
        q16, k16, DIMV, bqk, gamma, beta, 0, 0.0f);

    // 4. qkT per batch (K=128, single stage): A16 = fp16(relu(./L)^2 * 2^40)
    tgemm<1,1,128,1><<<dim3(LSEQ / 128, LSEQ / 128, NB), 256, SM_Q>>>(
        q16, QKD / 16, (size_t)LSEQ * QKD, (const uint32_t*)k16, QKD / 2,
        (size_t)LSEQ * (QKD / 2),
        A16, nullptr, QKD, nullptr, nullptr, nullptr, 0, 1.0f / LSEQ);

    // 5. AV per batch: V = (A@v) * 2^-40 * gate
    tgemm<2,0,64,3><<<dim3(HIDV / 128, LSEQ / 128, NB), 256, SM_P>>>(
        A16, LSEQ / 16, (size_t)LSEQ * LSEQ, (const uint32_t*)v16, HIDV,
        (size_t)LSEQ * (HIDV / 2),
        V, nullptr, LSEQ, gate, nullptr, nullptr, (size_t)LSEQ * HIDV, 0.0f);

    // 6. out = V @ Wo + bo
    out_kernel<<<ROWS / 8, 256>>>(V, Wo, bo, out);
}

// round 11
// speedup vs baseline: 1.8375x; 1.0363x over previous
#include <cuda_runtime.h>
#include <cuda_fp16.h>
#include <cstdint>

// Problem constants
#define NB     4
#define LSEQ   4096
#define ROWS   16384
#define DIMV   512
#define HID2   2048
#define HIDV   1024
#define QKD    128
#define OUTD   8

#define A_SCALE 1099511627776.0f        // 2^40  (exact)
#define A_INV   9.094947017729282e-13f  // 2^-40 (exact)

// ------------------------- scratch (static device globals) -------------------
__device__ __half g_normed[(size_t)ROWS * DIMV];     // quad16 layout
__device__ __half g_Wh16 [(size_t)DIMV * HID2];      // plain [k][n]
__device__ __half g_Wqk16[(size_t)DIMV * QKD];       // plain [k][n]
__device__ __half g_v16  [(size_t)ROWS * HIDV];      // plain [token][n]
__device__ float  g_gate [(size_t)ROWS * HIDV];      // fp32
__device__ __half g_q16  [(size_t)ROWS * QKD];       // quad16 layout
__device__ __half g_k16  [(size_t)ROWS * QKD];       // plain [token][128]
__device__ __half g_A16  [(size_t)NB * LSEQ * LSEQ]; // quad16 per batch (xA_SCALE)
__device__ float  g_V    [(size_t)ROWS * HIDV];      // fp32

// ------------------------------ helpers --------------------------------------
__device__ __forceinline__ uint32_t smem_u32(const void* p) {
    uint32_t a;
    asm("{ .reg .u64 t; cvta.to.shared.u64 t, %1; cvt.u32.u64 %0, t; }" : "=r"(a) : "l"(p));
    return a;
}
__device__ __forceinline__ void cp16(uint32_t s, const void* g) {
    asm volatile("cp.async.cg.shared.global [%0], [%1], 16;" :: "r"(s), "l"(g));
}
#define CP_COMMIT() asm volatile("cp.async.commit_group;" ::: "memory")
#define CP_WAIT0()  asm volatile("cp.async.wait_group 0;" ::: "memory")
#define CP_WAIT1()  asm volatile("cp.async.wait_group 1;" ::: "memory")

__device__ __forceinline__ void mma_f16(float* c, const uint32_t* a, const uint32_t* b) {
    asm volatile(
        "mma.sync.aligned.m16n8k16.row.col.f32.f16.f16.f32 "
        "{%0,%1,%2,%3},{%4,%5,%6,%7},{%8,%9},{%0,%1,%2,%3};"
        : "+f"(c[0]), "+f"(c[1]), "+f"(c[2]), "+f"(c[3])
        : "r"(a[0]), "r"(a[1]), "r"(a[2]), "r"(a[3]), "r"(b[0]), "r"(b[1]));
}
__device__ __forceinline__ void ldsm_x4_t(uint32_t* r, uint32_t addr) {
    asm volatile("ldmatrix.sync.aligned.m8n8.x4.trans.shared.b16 {%0,%1,%2,%3}, [%4];"
        : "=r"(r[0]), "=r"(r[1]), "=r"(r[2]), "=r"(r[3]) : "r"(addr));
}
__device__ __forceinline__ void ldsm_x4(uint32_t* r, uint32_t addr) {
    asm volatile("ldmatrix.sync.aligned.m8n8.x4.shared.b16 {%0,%1,%2,%3}, [%4];"
        : "=r"(r[0]), "=r"(r[1]), "=r"(r[2]), "=r"(r[3]) : "r"(addr));
}

// quad16 A-layout: 16m x 16k blocks of 256 halves; a thread's m16n8k16 A
// fragment (8 halves) is contiguous (1 LDS.128).
__device__ __forceinline__ size_t q16_off(int m, int k, int K16) {
    return ((size_t)(m >> 4) * K16 + (k >> 4)) * 256
         + (size_t)((((m & 7) << 2) + ((k & 7) >> 1)) * 8
                    + ((k >> 3) & 1) * 4 + ((m >> 3) & 1) * 2 + (k & 1));
}
__device__ __forceinline__ uint32_t packh2(float a, float b) {
    __half2 h = __floats2half2_rn(a, b);
    return *(uint32_t*)&h;
}

// ------------------------------ LayerNorm (quad16 fp16 out) ------------------
__global__ void ln_kernel(const float* __restrict__ x, const float* __restrict__ g,
                          const float* __restrict__ b, __half* __restrict__ o) {
    int row = blockIdx.x;
    int t = threadIdx.x;
    const float4* xr = (const float4*)(x + (size_t)row * DIMV);
    float4 xv = xr[t];
    float s  = xv.x + xv.y + xv.z + xv.w;
    float ss = xv.x*xv.x + xv.y*xv.y + xv.z*xv.z + xv.w*xv.w;
    #pragma unroll
    for (int off = 16; off; off >>= 1) {
        s  += __shfl_xor_sync(0xffffffffu, s,  off);
        ss += __shfl_xor_sync(0xffffffffu, ss, off);
    }
    __shared__ float sh_s[4], sh_ss[4];
    if ((t & 31) == 0) { sh_s[t >> 5] = s; sh_ss[t >> 5] = ss; }
    __syncthreads();
    s  = sh_s[0] + sh_s[1] + sh_s[2] + sh_s[3];
    ss = sh_ss[0] + sh_ss[1] + sh_ss[2] + sh_ss[3];
    float mu  = s * (1.0f / DIMV);
    float var = ss * (1.0f / DIMV) - mu * mu;
    float inv = rsqrtf(var + 1e-5f);
    float4 gv = ((const float4*)g)[t];
    float4 bv = ((const float4*)b)[t];
    float r0 = (xv.x - mu) * inv * gv.x + bv.x;
    float r1 = (xv.y - mu) * inv * gv.y + bv.y;
    float r2 = (xv.z - mu) * inv * gv.z + bv.z;
    float r3 = (xv.w - mu) * inv * gv.w + bv.w;
    int d0 = t * 4;
    *(uint32_t*)(o + q16_off(row, d0,     DIMV / 16)) = packh2(r0, r1);
    *(uint32_t*)(o + q16_off(row, d0 + 2, DIMV / 16)) = packh2(r2, r3);
}

// --------------------------- fp16 rounding copy (plain) ----------------------
__global__ void round16(const float* __restrict__ s, __half* __restrict__ d, int n) {
    int i = blockIdx.x * blockDim.x + threadIdx.x;
    if (i < n) d[i] = __float2half_rn(s[i]);
}

// --------------------------- fp16 tensor-core GEMM ---------------------------
// D[m][n] = sum_k A[m][k]*B[k][n];  A quad16 (LDS.128 frags), acc fp32.
// B smem: plain rows, pitch 136 halves (conflict-free ldmatrix).
// BL=0: B global [k][n]      -> ldmatrix.x4.trans  (rows = k)
// BL=1: B global [token][k]  -> ldmatrix.x4        (rows = token n)
// CTA 128x128, 8 warps, warp tile 64x32. NST=3: one-barrier pipeline; NST=1 single.
// EPI 0 (Wh): s=silu(acc+a0[n]); n<HIDV -> v16 plain; else gate fp32
// EPI 1 (qkT): A16 quad16 = fp16(relu(acc*scale)^2 * A_SCALE)
// EPI 2 (AV): V = acc * A_INV * gate[(z*4096+m)*HIDV+n]
// EPI 3 (Z):  s=silu(acc+a0[n]); q16 quad16; k16 plain
template<int EPI, int BL, int BK, int NST>
__global__ void __launch_bounds__(256, 2)
tgemm(const __half* __restrict__ Ag, int K16g, size_t sA,
      const __half* __restrict__ Bh, int ldbh, size_t sBh,
      void* __restrict__ C0, void* __restrict__ C1,
      int K,
      const float* __restrict__ a0, const float* __restrict__ a1,
      const float* __restrict__ a2, size_t sAux, float scale)
{
    constexpr int KB16   = BK / 16;
    constexpr int ASTG_H = 128 * BK;                       // halves per A stage
    constexpr int BROWS  = BL ? 128 : BK;
    constexpr int BSTG_H = BROWS * 136;

    extern __shared__ __half smh[];
    __half* Asm = smh;
    __half* Bsm = smh + NST * ASTG_H;
    const uint32_t sbA = smem_u32(Asm);
    const uint32_t sbB = smem_u32(Bsm);
    (void)sbA;

    const int z = blockIdx.z;
    const __half* A = Ag + z * sA;
    const __half* B = Bh + z * sBh;
    const float* ax = a0 + z * sAux;

    const int tid  = threadIdx.x;
    const int warp = tid >> 5;
    const int lane = tid & 31;
    const int grp  = lane >> 2;
    const int tig  = lane & 3;
    const int mw   = (warp >> 2) * 64;
    const int nw   = (warp & 3) * 32;
    const int m0 = blockIdx.y * 128, n0 = blockIdx.x * 128;
    const int mbb = (mw >> 4);

    // per-lane ldmatrix base offset (halves, within a stage)
    const int bOff = BL
        ? ((nw + (lane & 7) + 8 * (lane >> 4)) * 136 + 8 * ((lane >> 3) & 1))
        : ((lane & 15) * 136 + (lane >> 4) * 8 + nw);

    float acc[4][4][4];
    #pragma unroll
    for (int mi = 0; mi < 4; mi++)
        #pragma unroll
        for (int ni = 0; ni < 4; ni++)
            #pragma unroll
            for (int r = 0; r < 4; r++) acc[mi][ni][r] = 0.0f;

    auto load_stage = [&](int st, int k0) {
        // A: quad16 blocks, 16B chunks
        #pragma unroll
        for (int l = 0; l < BK / 16; l++) {
            int qc = tid + l * 256;
            int blk = qc >> 5, c = qc & 31;
            int mbl = blk / KB16, kbl = blk - mbl * KB16;
            const __half* gsrc = A + ((size_t)(m0 / 16 + mbl) * K16g + (k0 / 16 + kbl)) * 256 + c * 8;
            cp16(sbB - (NST * ASTG_H - (uint32_t)(st * ASTG_H + blk * 256 + c * 8)) * 2 - 0 + 0
                 , gsrc);
        }
        // B: BROWS rows x 128 halves, 16 chunks/row
        if (BL == 0) {
            #pragma unroll
            for (int l = 0; l < BK / 16; l++) {
                int id = tid + l * 256;
                int r = id >> 4, c = id & 15;
                cp16(sbB + (uint32_t)(st * BSTG_H + r * 136 + c * 8) * 2,
                     B + (size_t)(k0 + r) * ldbh + n0 + c * 8);
            }
        } else {
            #pragma unroll
            for (int l = 0; l < 8; l++) {
                int id = tid + l * 256;
                int r = id >> 4, c = id & 15;
                cp16(sbB + (uint32_t)(st * BSTG_H + r * 136 + c * 8) * 2,
                     B + (size_t)(n0 + r) * ldbh + k0 + c * 8);
            }
        }
        CP_COMMIT();
    };

    auto compute_stage = [&](int st) {
        const __half* As = Asm + st * ASTG_H;
        const uint32_t sbBs = sbB + (uint32_t)(st * BSTG_H) * 2;
        #pragma unroll
        for (int s = 0; s < KB16; s++) {
            uint32_t afr[4][4], bq0[4], bq1[4];
            #pragma unroll
            for (int mi = 0; mi < 4; mi++) {
                uint4 av = *(const uint4*)(As + (((mbb + mi) * KB16 + s) * 256 + lane * 8));
                afr[mi][0] = av.x; afr[mi][1] = av.y; afr[mi][2] = av.z; afr[mi][3] = av.w;
            }
            if (BL == 0) {
                ldsm_x4_t(bq0, sbBs + (uint32_t)(s * 2176 + bOff) * 2);
                ldsm_x4_t(bq1, sbBs + (uint32_t)(s * 2176 + bOff + 16) * 2);
            } else {
                ldsm_x4(bq0, sbBs + (uint32_t)(s * 16 + bOff) * 2);
                ldsm_x4(bq1, sbBs + (uint32_t)(s * 16 + bOff + 16 * 136) * 2);
            }
            uint32_t bfr[4][2] = {
                { bq0[0], bq0[1] }, { bq0[2], bq0[3] },
                { bq1[0], bq1[1] }, { bq1[2], bq1[3] } };
            #pragma unroll
            for (int mi = 0; mi < 4; mi++)
                #pragma unroll
                for (int ni = 0; ni < 4; ni++)
                    mma_f16(acc[mi][ni], afr[mi], bfr[ni]);
        }
    };

    const int niter = K / BK;
    if (NST == 1) {
        load_stage(0, 0);
        CP_WAIT0();
        __syncthreads();
        compute_stage(0);
    } else {
        load_stage(0, 0);
        if (niter > 1) load_stage(1, BK);
        for (int it = 0; it < niter; it++) {
            if (it + 1 < niter) { CP_WAIT1(); }
            else                { CP_WAIT0(); }
            __syncthreads();
            if (it + 2 < niter) load_stage((it + 2) % NST, (it + 2) * BK);
            compute_stage(it % NST);
        }
    }
    __syncthreads();

    // ------------------------------ epilogue ---------------------------------
    #pragma unroll
    for (int mi = 0; mi < 4; mi++) {
        #pragma unroll
        for (int half = 0; half < 2; half++) {
            int m = m0 + mw + mi * 16 + grp + half * 8;
            #pragma unroll
            for (int ni = 0; ni < 4; ni++) {
                int n = n0 + nw + ni * 8 + tig * 2;
                float v0 = acc[mi][ni][half * 2 + 0];
                float v1 = acc[mi][ni][half * 2 + 1];
                if (EPI == 0) {
                    v0 += a0[n];     v1 += a0[n + 1];
                    v0 = v0 / (1.0f + __expf(-v0));
                    v1 = v1 / (1.0f + __expf(-v1));
                    if (n < HIDV) {
                        __half* vv = (__half*)C0;
                        *(uint32_t*)(vv + (size_t)m * HIDV + n) = packh2(v0, v1);
                    } else {
                        float* gb = (float*)C1;
                        *(float2*)(gb + (size_t)m * HIDV + (n - HIDV)) = make_float2(v0, v1);
                    }
                } else if (EPI == 1) {
                    float t0 = fmaxf(v0 * scale, 0.0f);
                    float t1 = fmaxf(v1 * scale, 0.0f);
                    __half* Az = (__half*)C0 + (size_t)z * LSEQ * LSEQ;
                    *(uint32_t*)(Az + q16_off(m, n, LSEQ / 16)) =
                        packh2(t0 * t0 * A_SCALE, t1 * t1 * A_SCALE);
                } else if (EPI == 2) {
                    float* Vp = (float*)C0 + (size_t)z * LSEQ * HIDV;
                    v0 *= A_INV * ax[(size_t)m * HIDV + n];
                    v1 *= A_INV * ax[(size_t)m * HIDV + n + 1];
                    *(float2*)(Vp + (size_t)m * HIDV + n) = make_float2(v0, v1);
                } else {   // EPI 3
                    v0 += a0[n];     v1 += a0[n + 1];
                    v0 = v0 / (1.0f + __expf(-v0));
                    v1 = v1 / (1.0f + __expf(-v1));
                    __half* qb = (__half*)C0;
                    __half* kb = (__half*)C1;
                    *(uint32_t*)(qb + q16_off(m, n, QKD / 16)) =
                        packh2(v0 * a1[n] + a2[n], v1 * a1[n + 1] + a2[n + 1]);
                    *(uint32_t*)(kb + (size_t)m * QKD + n) =
                        packh2(v0 * a1[QKD + n] + a2[QKD + n],
                               v1 * a1[QKD + n + 1] + a2[QKD + n + 1]);
                }
            }
        }
    }
}

// ------------------------- output projection (1024 -> 8) ---------------------
__global__ void out_kernel(const float* __restrict__ Vg, const float* __restrict__ Wo,
                           const float* __restrict__ bo, float* __restrict__ out) {
    int row  = blockIdx.x * (blockDim.x >> 5) + (threadIdx.x >> 5);
    int lane = threadIdx.x & 31;
    const float* vr = Vg + (size_t)row * HIDV;
    float acc[OUTD];
    #pragma unroll
    for (int o = 0; o < OUTD; o++) acc[o] = 0.0f;
    for (int kk = lane; kk < HIDV; kk += 32) {
        float v = vr[kk];
        const float* w = Wo + (size_t)kk * OUTD;
        #pragma unroll
        for (int o = 0; o < OUTD; o++) acc[o] += v * w[o];
    }
    #pragma unroll
    for (int o = 0; o < OUTD; o++) {
        #pragma unroll
        for (int off = 16; off; off >>= 1)
            acc[o] += __shfl_xor_sync(0xffffffffu, acc[o], off);
    }
    if (lane < OUTD) out[(size_t)row * OUTD + lane] = acc[lane] + bo[lane];
}

// --------------------------------- launch ------------------------------------
extern "C" void kernel_launch(void* const* d_in, const int* in_sizes, int n_in,
                              void* d_out, int out_size) {
    const float* x     = (const float*)d_in[0];
    const float* ln_g  = (const float*)d_in[1];
    const float* ln_b  = (const float*)d_in[2];
    const float* Wh    = (const float*)d_in[3];
    const float* bh    = (const float*)d_in[4];
    const float* Wqk   = (const float*)d_in[5];
    const float* bqk   = (const float*)d_in[6];
    const float* gamma = (const float*)d_in[7];
    const float* beta  = (const float*)d_in[8];
    const float* Wo    = (const float*)d_in[9];
    const float* bo    = (const float*)d_in[10];
    float* out = (float*)d_out;

    __half *normed, *Wh16, *Wqk16, *v16, *q16, *k16, *A16;
    float *gate, *V;
    cudaGetSymbolAddress((void**)&normed, g_normed);
    cudaGetSymbolAddress((void**)&Wh16,   g_Wh16);
    cudaGetSymbolAddress((void**)&Wqk16,  g_Wqk16);
    cudaGetSymbolAddress((void**)&v16,    g_v16);
    cudaGetSymbolAddress((void**)&gate,   g_gate);
    cudaGetSymbolAddress((void**)&q16,    g_q16);
    cudaGetSymbolAddress((void**)&k16,    g_k16);
    cudaGetSymbolAddress((void**)&A16,    g_A16);
    cudaGetSymbolAddress((void**)&V,      g_V);

    // smem: BK64/NST3: (3*8192 + 3*8704)*2 = 101376 B
    //       BK128/NST1: (16384 + 17408)*2  = 67584 B
    const int SM_P = 101376, SM_Q = 67584;
    static bool attr_done = false;
    if (!attr_done) {
        cudaFuncSetAttribute(tgemm<0,0,64,3>,  cudaFuncAttributeMaxDynamicSharedMemorySize, SM_P);
        cudaFuncSetAttribute(tgemm<3,0,64,3>,  cudaFuncAttributeMaxDynamicSharedMemorySize, SM_P);
        cudaFuncSetAttribute(tgemm<1,1,128,1>, cudaFuncAttributeMaxDynamicSharedMemorySize, SM_Q);
        cudaFuncSetAttribute(tgemm<2,0,64,3>,  cudaFuncAttributeMaxDynamicSharedMemorySize, SM_P);
        attr_done = true;
    }

    // 0. weights -> fp16 (plain row-major)
    round16<<<(DIMV * HID2 + 255) / 256, 256>>>(Wh,  Wh16,  DIMV * HID2);
    round16<<<(DIMV * QKD  + 255) / 256, 256>>>(Wqk, Wqk16, DIMV * QKD);

    // 1. LayerNorm -> normed (quad16 fp16)
    ln_kernel<<<ROWS, 128>>>(x, ln_g, ln_b, normed);

    // 2. Wh GEMM: hidden -> v16 (plain) + gate (fp32)
    tgemm<0,0,64,3><<<dim3(HID2 / 128, ROWS / 128, 1), 256, SM_P>>>(
        normed, DIMV / 16, 0, Wh16, HID2, 0,
        v16, gate, DIMV, bh, nullptr, nullptr, 0, 0.0f);

    // 3. Z GEMM fused silu + affine -> q16 (quad16), k16 (plain)
    tgemm<3,0,64,3><<<dim3(1, ROWS / 128, 1), 256, SM_P>>>(
        normed, DIMV / 16, 0, Wqk16, QKD, 0,
        q16, k16, DIMV, bqk, gamma, beta, 0, 0.0f);

    // 4. qkT per batch (K=128, single stage): A16 = fp16(relu(./L)^2 * 2^40)
    tgemm<1,1,128,1><<<dim3(LSEQ / 128, LSEQ / 128, NB), 256, SM_Q>>>(
        q16, QKD / 16, (size_t)LSEQ * QKD, k16, QKD, (size_t)LSEQ * QKD,
        A16, nullptr, QKD, nullptr, nullptr, nullptr, 0, 1.0f / LSEQ);

    // 5. AV per batch: V = (A@v) * 2^-40 * gate
    tgemm<2,0,64,3><<<dim3(HIDV / 128, LSEQ / 128, NB), 256, SM_P>>>(
        A16, LSEQ / 16, (size_t)LSEQ * LSEQ, v16, HIDV, (size_t)LSEQ * HIDV,
        V, nullptr, LSEQ, gate, nullptr, nullptr, (size_t)LSEQ * HIDV, 0.0f);

    // 6. out = V @ Wo + bo
    out_kernel<<<ROWS / 8, 256>>>(V, Wo, bo, out);
}